// round 3
// baseline (speedup 1.0000x reference)
#include <cuda_runtime.h>
#include <math.h>

#define NB    8
#define DIM   256
#define YD    4096
#define HH    8
#define INNER 512
#define WW    256
#define ASCALE 0.125f

typedef unsigned long long u64;

__device__ __forceinline__ u64 ffma2(u64 a, u64 b, u64 c) {
    u64 d; asm("fma.rn.f32x2 %0, %1, %2, %3;" : "=l"(d) : "l"(a), "l"(b), "l"(c)); return d;
}
__device__ __forceinline__ u64 dup2(float x) {
    u64 d; asm("mov.b64 %0, {%1, %2};" : "=l"(d) : "f"(x), "f"(x)); return d;
}
__device__ __forceinline__ float2 u2f(u64 v) {
    float2 r; asm("mov.b64 {%0, %1}, %2;" : "=f"(r.x), "=f"(r.y) : "l"(v)); return r;
}

// ---------------- scratch ----------------
__device__ float g_Q0[NB * INNER * YD];
__device__ float g_Q1[NB * INNER * YD];
__device__ float g_KV0[NB * 2 * INNER * WW];
__device__ float g_KV1[NB * 2 * INNER * WW];
__device__ float g_O0[(size_t)NB * YD * INNER];
__device__ float g_O1[(size_t)NB * YD * INNER];

// =====================================================================
// Q projection (both streams). C[b,m,n] = sum_k A[m,k] X[b,k,n]
// M=512,K=256,N=4096. 128x128 tile, BK=8, micro 8m x 8n (m packed pairs).
// =====================================================================
__global__ __launch_bounds__(256) void qproj_kernel(
    const float* __restrict__ A0, const float* __restrict__ X0, float* __restrict__ C0,
    const float* __restrict__ A1, const float* __restrict__ X1, float* __restrict__ C1)
{
    const int K = DIM, N = YD;
    const int z = blockIdx.z;
    const int b = z & 7;
    const float* A  = (z < NB) ? A0 : A1;
    const float* Bp = ((z < NB) ? X0 : X1) + (size_t)b * K * N;
    float*       Cp = ((z < NB) ? C0 : C1) + (size_t)b * INNER * N;
    const int n0 = blockIdx.x * 128;
    const int m0 = blockIdx.y * 128;

    __shared__ float As[8][132];
    __shared__ float Bs[8][128];

    const int t = threadIdx.x, tx = t & 15, ty = t >> 4;

    u64 acc[4][8];
#pragma unroll
    for (int i = 0; i < 4; i++)
#pragma unroll
        for (int j = 0; j < 8; j++) acc[i][j] = 0ULL;

    for (int k0 = 0; k0 < K; k0 += 8) {
        {   int m = t >> 1, k4 = (t & 1) * 4;
            float4 a = *(const float4*)&A[(m0 + m) * K + k0 + k4];
            As[k4 + 0][m] = a.x; As[k4 + 1][m] = a.y;
            As[k4 + 2][m] = a.z; As[k4 + 3][m] = a.w;
        }
        {   int kk = t >> 5, n4 = (t & 31) * 4;
            *(float4*)&Bs[kk][n4] = *(const float4*)&Bp[(size_t)(k0 + kk) * N + n0 + n4];
        }
        __syncthreads();
#pragma unroll
        for (int k = 0; k < 8; k++) {
            ulonglong2 av0 = *(const ulonglong2*)&As[k][ty * 8];
            ulonglong2 av1 = *(const ulonglong2*)&As[k][ty * 8 + 4];
            u64 a2[4] = { av0.x, av0.y, av1.x, av1.y };
            float4 b0 = *(const float4*)&Bs[k][tx * 4];
            float4 b1 = *(const float4*)&Bs[k][64 + tx * 4];
            u64 bd[8] = { dup2(b0.x), dup2(b0.y), dup2(b0.z), dup2(b0.w),
                          dup2(b1.x), dup2(b1.y), dup2(b1.z), dup2(b1.w) };
#pragma unroll
            for (int ip = 0; ip < 4; ip++)
#pragma unroll
                for (int jj = 0; jj < 8; jj++)
                    acc[ip][jj] = ffma2(a2[ip], bd[jj], acc[ip][jj]);
        }
        __syncthreads();
    }
#pragma unroll
    for (int ip = 0; ip < 4; ip++) {
        int r0 = m0 + ty * 8 + 2 * ip;
#pragma unroll
        for (int c = 0; c < 2; c++) {
            float4 lo, hi;
            float2 f0 = u2f(acc[ip][c * 4 + 0]), f1 = u2f(acc[ip][c * 4 + 1]);
            float2 f2 = u2f(acc[ip][c * 4 + 2]), f3 = u2f(acc[ip][c * 4 + 3]);
            lo.x = f0.x; lo.y = f1.x; lo.z = f2.x; lo.w = f3.x;
            hi.x = f0.y; hi.y = f1.y; hi.z = f2.y; hi.w = f3.y;
            size_t col = n0 + 64 * c + tx * 4;
            *(float4*)&Cp[(size_t)r0 * N + col]       = lo;
            *(float4*)&Cp[(size_t)(r0 + 1) * N + col] = hi;
        }
    }
}

// =====================================================================
// KV projection (both streams). M=1024,N=256(w),K=4096. BM=128,BN=64,BK=16.
// micro 8m x 4n, m packed pairs.
// =====================================================================
__global__ __launch_bounds__(256) void kvproj_kernel(
    const float* __restrict__ W0, const float* __restrict__ X0, float* __restrict__ C0,
    const float* __restrict__ W1, const float* __restrict__ X1, float* __restrict__ C1)
{
    const int M = 2 * INNER, N = WW, K = DIM * 16;
    const int z = blockIdx.z;
    const int b = z & 7;
    const float* Wkv = (z < NB) ? W0 : W1;
    const float* xp  = ((z < NB) ? X0 : X1) + (size_t)b * DIM * YD;
    float*       Cp  = ((z < NB) ? C0 : C1) + (size_t)b * M * N;
    const int n0 = blockIdx.x * 64;
    const int m0 = blockIdx.y * 128;

    __shared__ float As[16][132];
    __shared__ float Bs[16][68];

    const int t = threadIdx.x, tx = t & 15, ty = t >> 4;

    u64 acc[4][4];
#pragma unroll
    for (int i = 0; i < 4; i++)
#pragma unroll
        for (int j = 0; j < 4; j++) acc[i][j] = 0ULL;

    for (int nt = 0; nt < DIM; nt++) {
        const int k0 = nt * 16;
        {   int m = t >> 1, k8 = (t & 1) * 8;
            float4 a0 = *(const float4*)&Wkv[(size_t)(m0 + m) * K + k0 + k8];
            float4 a1 = *(const float4*)&Wkv[(size_t)(m0 + m) * K + k0 + k8 + 4];
            As[k8 + 0][m] = a0.x; As[k8 + 1][m] = a0.y;
            As[k8 + 2][m] = a0.z; As[k8 + 3][m] = a0.w;
            As[k8 + 4][m] = a1.x; As[k8 + 5][m] = a1.y;
            As[k8 + 6][m] = a1.z; As[k8 + 7][m] = a1.w;
        }
        {   const float* src = xp + (size_t)nt * YD + n0 * 16;
            float4 v = *(const float4*)&src[t * 4];
            int w = t >> 2, pq0 = (t & 3) * 4;
            Bs[pq0 + 0][w] = v.x; Bs[pq0 + 1][w] = v.y;
            Bs[pq0 + 2][w] = v.z; Bs[pq0 + 3][w] = v.w;
        }
        __syncthreads();
#pragma unroll
        for (int k = 0; k < 16; k++) {
            ulonglong2 av0 = *(const ulonglong2*)&As[k][ty * 8];
            ulonglong2 av1 = *(const ulonglong2*)&As[k][ty * 8 + 4];
            u64 a2[4] = { av0.x, av0.y, av1.x, av1.y };
            float4 bb = *(const float4*)&Bs[k][tx * 4];
            u64 bd[4] = { dup2(bb.x), dup2(bb.y), dup2(bb.z), dup2(bb.w) };
#pragma unroll
            for (int ip = 0; ip < 4; ip++)
#pragma unroll
                for (int jj = 0; jj < 4; jj++)
                    acc[ip][jj] = ffma2(a2[ip], bd[jj], acc[ip][jj]);
        }
        __syncthreads();
    }
#pragma unroll
    for (int ip = 0; ip < 4; ip++) {
        int r0 = m0 + ty * 8 + 2 * ip;
        float4 lo, hi;
        float2 f0 = u2f(acc[ip][0]), f1 = u2f(acc[ip][1]);
        float2 f2 = u2f(acc[ip][2]), f3 = u2f(acc[ip][3]);
        lo.x = f0.x; lo.y = f1.x; lo.z = f2.x; lo.w = f3.x;
        hi.x = f0.y; hi.y = f1.y; hi.z = f2.y; hi.w = f3.y;
        *(float4*)&Cp[(size_t)r0 * N + n0 + tx * 4]       = lo;
        *(float4*)&Cp[(size_t)(r0 + 1) * N + n0 + tx * 4] = hi;
    }
}

// =====================================================================
// Attention (both streams): per CTA (64 q rows, h, b, stream).
// K,V staged [d][j] (no transpose), dots block-GEMM micro 4i x 16j,
// softmax via 16-lane shfl, P -> SMEM, PV pairwise-f32x2 micro 4i x 4d.
// =====================================================================
__global__ __launch_bounds__(256) void attn_kernel(
    const float* __restrict__ Q0, const float* __restrict__ KVa, float* __restrict__ O0,
    const float* __restrict__ Q1, const float* __restrict__ KVb, float* __restrict__ O1)
{
    const int z = blockIdx.z;
    const int b = z & 7;
    const float* Q  = (z < NB) ? Q0 : Q1;
    const float* KV = (z < NB) ? KVa : KVb;   // stream0 attends KV1, stream1 attends KV0
    float*       O  = (z < NB) ? O0 : O1;
    const int h  = blockIdx.y;
    const int i0 = blockIdx.x * 64;

    extern __shared__ float sm[];
    float* ks = sm;                    // [64][260]
    float* vs = ks + 64 * 260;         // [64][260]
    float* ps = vs + 64 * 260;         // [64][260]
    float* qs = ps + 64 * 260;         // [64][68]  (qs[d][i])

    const int t = threadIdx.x, tx = t & 15, ty = t >> 4;

    const float* Kb = KV + ((size_t)b * 1024 + h * 64) * WW;
    const float* Vb = KV + ((size_t)b * 1024 + 512 + h * 64) * WW;

    for (int idx = t; idx < 64 * 64; idx += 256) {
        int d = idx >> 6, j4 = (idx & 63) * 4;
        *(float4*)&ks[d * 260 + j4] = *(const float4*)&Kb[d * WW + j4];
        *(float4*)&vs[d * 260 + j4] = *(const float4*)&Vb[d * WW + j4];
    }
    for (int idx = t; idx < 64 * 16; idx += 256) {
        int d = idx >> 4, i4 = (idx & 15) * 4;
        *(float4*)&qs[d * 68 + i4] =
            *(const float4*)&Q[((size_t)b * INNER + h * 64 + d) * YD + i0 + i4];
    }
    __syncthreads();

    // ---- dots: rows i = ty*4+ii, cols j = 64*c + tx*4 + w ----
    u64 s2[4][8];
#pragma unroll
    for (int i = 0; i < 4; i++)
#pragma unroll
        for (int j = 0; j < 8; j++) s2[i][j] = 0ULL;

#pragma unroll 8
    for (int d = 0; d < 64; d++) {
        float4 q4 = *(const float4*)&qs[d * 68 + ty * 4];
        u64 qd[4] = { dup2(q4.x), dup2(q4.y), dup2(q4.z), dup2(q4.w) };
#pragma unroll
        for (int c = 0; c < 4; c++) {
            ulonglong2 kk = *(const ulonglong2*)&ks[d * 260 + c * 64 + tx * 4];
#pragma unroll
            for (int ii = 0; ii < 4; ii++) {
                s2[ii][c * 2 + 0] = ffma2(qd[ii], kk.x, s2[ii][c * 2 + 0]);
                s2[ii][c * 2 + 1] = ffma2(qd[ii], kk.y, s2[ii][c * 2 + 1]);
            }
        }
    }

    // ---- softmax over j (row spread across 16 tx lanes) ----
    float p[4][16];
#pragma unroll
    for (int ii = 0; ii < 4; ii++) {
        float mx = -1e30f;
#pragma unroll
        for (int jp = 0; jp < 8; jp++) {
            float2 f = u2f(s2[ii][jp]);
            p[ii][jp * 2 + 0] = f.x * ASCALE;
            p[ii][jp * 2 + 1] = f.y * ASCALE;
            mx = fmaxf(mx, fmaxf(p[ii][jp * 2], p[ii][jp * 2 + 1]));
        }
#pragma unroll
        for (int off = 8; off; off >>= 1)
            mx = fmaxf(mx, __shfl_xor_sync(0xffffffffu, mx, off));
        float s = 0.f;
#pragma unroll
        for (int w = 0; w < 16; w++) { p[ii][w] = __expf(p[ii][w] - mx); s += p[ii][w]; }
#pragma unroll
        for (int off = 8; off; off >>= 1)
            s += __shfl_xor_sync(0xffffffffu, s, off);
        float inv = 1.f / s;
#pragma unroll
        for (int w = 0; w < 16; w++) p[ii][w] *= inv;
    }
#pragma unroll
    for (int ii = 0; ii < 4; ii++) {
        int row = ty * 4 + ii;
#pragma unroll
        for (int c = 0; c < 4; c++) {
            float4 v;
            v.x = p[ii][c * 4 + 0]; v.y = p[ii][c * 4 + 1];
            v.z = p[ii][c * 4 + 2]; v.w = p[ii][c * 4 + 3];
            *(float4*)&ps[row * 260 + c * 64 + tx * 4] = v;
        }
    }
    __syncthreads();

    // ---- PV pairwise: o[i][d], i = ty*4+ii, d = tx + 16r ----
    u64 o2[4][4];
#pragma unroll
    for (int i = 0; i < 4; i++)
#pragma unroll
        for (int j = 0; j < 4; j++) o2[i][j] = 0ULL;

#pragma unroll 8
    for (int j = 0; j < 256; j += 4) {
        ulonglong2 av[4], bv[4];
#pragma unroll
        for (int ii = 0; ii < 4; ii++)
            av[ii] = *(const ulonglong2*)&ps[(ty * 4 + ii) * 260 + j];
#pragma unroll
        for (int r = 0; r < 4; r++)
            bv[r] = *(const ulonglong2*)&vs[(tx + 16 * r) * 260 + j];
#pragma unroll
        for (int ii = 0; ii < 4; ii++)
#pragma unroll
            for (int r = 0; r < 4; r++) {
                o2[ii][r] = ffma2(av[ii].x, bv[r].x, o2[ii][r]);
                o2[ii][r] = ffma2(av[ii].y, bv[r].y, o2[ii][r]);
            }
    }
#pragma unroll
    for (int ii = 0; ii < 4; ii++) {
        size_t base = (((size_t)b * YD + i0 + ty * 4 + ii) * HH + h) * 64;
#pragma unroll
        for (int r = 0; r < 4; r++) {
            float2 f = u2f(o2[ii][r]);
            O[base + tx + 16 * r] = f.x + f.y;
        }
    }
}

// =====================================================================
// Out proj (NT, both phases) + residual fuse. M=256,N=4096,K=512x2.
// micro 8m x 8n, m packed pairs.
// =====================================================================
__global__ __launch_bounds__(256) void outproj_kernel(
    const float* __restrict__ W0, const float* __restrict__ O0,
    const float* __restrict__ W1, const float* __restrict__ O1,
    const float* __restrict__ b0, const float* __restrict__ b1,
    const float* __restrict__ x0, const float* __restrict__ x1,
    float* __restrict__ out)
{
    const int b  = blockIdx.z;
    const int n0 = blockIdx.x * 128;
    const int m0 = blockIdx.y * 128;

    __shared__ float Ws[16][132];
    __shared__ float Bs[16][132];

    const int t = threadIdx.x, tx = t & 15, ty = t >> 4;

    u64 acc[4][8];
#pragma unroll
    for (int i = 0; i < 4; i++)
#pragma unroll
        for (int j = 0; j < 8; j++) acc[i][j] = 0ULL;

    const float* Ops[2]  = { O0 + (size_t)b * YD * INNER, O1 + (size_t)b * YD * INNER };
    const float* Wsrc[2] = { W0, W1 };

    for (int ph = 0; ph < 2; ph++) {
        const float* W  = Wsrc[ph];
        const float* Op = Ops[ph];
        for (int k0 = 0; k0 < INNER; k0 += 16) {
            {   int m = t >> 1, k8 = (t & 1) * 8;
                float4 a0 = *(const float4*)&W[(size_t)(m0 + m) * INNER + k0 + k8];
                float4 a1 = *(const float4*)&W[(size_t)(m0 + m) * INNER + k0 + k8 + 4];
                Ws[k8 + 0][m] = a0.x; Ws[k8 + 1][m] = a0.y;
                Ws[k8 + 2][m] = a0.z; Ws[k8 + 3][m] = a0.w;
                Ws[k8 + 4][m] = a1.x; Ws[k8 + 5][m] = a1.y;
                Ws[k8 + 6][m] = a1.z; Ws[k8 + 7][m] = a1.w;
            }
            {   int n = t >> 1, k8 = (t & 1) * 8;
                float4 a0 = *(const float4*)&Op[(size_t)(n0 + n) * INNER + k0 + k8];
                float4 a1 = *(const float4*)&Op[(size_t)(n0 + n) * INNER + k0 + k8 + 4];
                Bs[k8 + 0][n] = a0.x; Bs[k8 + 1][n] = a0.y;
                Bs[k8 + 2][n] = a0.z; Bs[k8 + 3][n] = a0.w;
                Bs[k8 + 4][n] = a1.x; Bs[k8 + 5][n] = a1.y;
                Bs[k8 + 6][n] = a1.z; Bs[k8 + 7][n] = a1.w;
            }
            __syncthreads();
#pragma unroll
            for (int k = 0; k < 16; k++) {
                ulonglong2 av0 = *(const ulonglong2*)&Ws[k][ty * 8];
                ulonglong2 av1 = *(const ulonglong2*)&Ws[k][ty * 8 + 4];
                u64 a2[4] = { av0.x, av0.y, av1.x, av1.y };
                float4 c0 = *(const float4*)&Bs[k][tx * 4];
                float4 c1 = *(const float4*)&Bs[k][64 + tx * 4];
                u64 bd[8] = { dup2(c0.x), dup2(c0.y), dup2(c0.z), dup2(c0.w),
                              dup2(c1.x), dup2(c1.y), dup2(c1.z), dup2(c1.w) };
#pragma unroll
                for (int ip = 0; ip < 4; ip++)
#pragma unroll
                    for (int jj = 0; jj < 8; jj++)
                        acc[ip][jj] = ffma2(a2[ip], bd[jj], acc[ip][jj]);
            }
            __syncthreads();
        }
    }

#pragma unroll
    for (int ip = 0; ip < 4; ip++) {
        int r0 = m0 + ty * 8 + 2 * ip;
        float bias0 = 0.5f * (b0[r0] + b1[r0]);
        float bias1 = 0.5f * (b0[r0 + 1] + b1[r0 + 1]);
#pragma unroll
        for (int c = 0; c < 2; c++) {
            float4 lo, hi;
            float2 f0 = u2f(acc[ip][c * 4 + 0]), f1 = u2f(acc[ip][c * 4 + 1]);
            float2 f2 = u2f(acc[ip][c * 4 + 2]), f3 = u2f(acc[ip][c * 4 + 3]);
            lo.x = f0.x; lo.y = f1.x; lo.z = f2.x; lo.w = f3.x;
            hi.x = f0.y; hi.y = f1.y; hi.z = f2.y; hi.w = f3.y;
            size_t col = n0 + 64 * c + tx * 4;
            size_t i0x = ((size_t)b * DIM + r0) * YD + col;
            size_t i1x = ((size_t)b * DIM + r0 + 1) * YD + col;
            float4 xa0 = *(const float4*)&x0[i0x], xb0 = *(const float4*)&x1[i0x];
            float4 xa1 = *(const float4*)&x0[i1x], xb1 = *(const float4*)&x1[i1x];
            float4 r;
            r.x = 0.5f * (lo.x + xa0.x + xb0.x) + bias0;
            r.y = 0.5f * (lo.y + xa0.y + xb0.y) + bias0;
            r.z = 0.5f * (lo.z + xa0.z + xb0.z) + bias0;
            r.w = 0.5f * (lo.w + xa0.w + xb0.w) + bias0;
            *(float4*)&out[i0x] = r;
            r.x = 0.5f * (hi.x + xa1.x + xb1.x) + bias1;
            r.y = 0.5f * (hi.y + xa1.y + xb1.y) + bias1;
            r.z = 0.5f * (hi.z + xa1.z + xb1.z) + bias1;
            r.w = 0.5f * (hi.w + xa1.w + xb1.w) + bias1;
            *(float4*)&out[i1x] = r;
        }
    }
}

// =====================================================================
extern "C" void kernel_launch(void* const* d_in, const int* in_sizes, int n_in,
                              void* d_out, int out_size)
{
    const float* x0    = (const float*)d_in[0];
    const float* x1    = (const float*)d_in[1];
    const float* Wq0   = (const float*)d_in[2];
    const float* Wkv0  = (const float*)d_in[3];
    const float* Wq1   = (const float*)d_in[4];
    const float* Wkv1  = (const float*)d_in[5];
    const float* Wout0 = (const float*)d_in[6];
    const float* bout0 = (const float*)d_in[7];
    const float* Wout1 = (const float*)d_in[8];
    const float* bout1 = (const float*)d_in[9];
    float* out = (float*)d_out;

    float *Q0, *Q1, *KV0, *KV1, *O0, *O1;
    cudaGetSymbolAddress((void**)&Q0,  g_Q0);
    cudaGetSymbolAddress((void**)&Q1,  g_Q1);
    cudaGetSymbolAddress((void**)&KV0, g_KV0);
    cudaGetSymbolAddress((void**)&KV1, g_KV1);
    cudaGetSymbolAddress((void**)&O0,  g_O0);
    cudaGetSymbolAddress((void**)&O1,  g_O1);

    const int attn_smem = (3 * 64 * 260 + 64 * 68) * (int)sizeof(float);   // 217088
    cudaFuncSetAttribute(attn_kernel, cudaFuncAttributeMaxDynamicSharedMemorySize, attn_smem);

    dim3 blk(256);
    qproj_kernel<<<dim3(YD / 128, INNER / 128, 2 * NB), blk>>>(Wq0, x0, Q0, Wq1, x1, Q1);
    kvproj_kernel<<<dim3(WW / 64, (2 * INNER) / 128, 2 * NB), blk>>>(Wkv0, x0, KV0, Wkv1, x1, KV1);
    // stream0: attend(Q0, KV1) -> O0 ; stream1: attend(Q1, KV0) -> O1
    attn_kernel<<<dim3(YD / 64, HH, 2 * NB), blk, attn_smem>>>(Q0, KV1, O0, Q1, KV0, O1);
    outproj_kernel<<<dim3(YD / 128, DIM / 128, NB), blk>>>(
        Wout0, O0, Wout1, O1, bout0, bout1, x0, x1, out);
}

// round 5
// speedup vs baseline: 1.5276x; 1.5276x over previous
#include <cuda_runtime.h>
#include <math.h>
#include <cstdint>

#define NB    8
#define DIM   256
#define YD    4096
#define HH    8
#define INNER 512
#define WW    256
#define ASCALE 0.125f

typedef unsigned long long u64;

// ---------------- f32x2 helpers (attention kernel) ----------------
__device__ __forceinline__ u64 ffma2(u64 a, u64 b, u64 c) {
    u64 d; asm("fma.rn.f32x2 %0, %1, %2, %3;" : "=l"(d) : "l"(a), "l"(b), "l"(c)); return d;
}
__device__ __forceinline__ u64 dup2(float x) {
    u64 d; asm("mov.b64 %0, {%1, %2};" : "=l"(d) : "f"(x), "f"(x)); return d;
}
__device__ __forceinline__ float2 u2f(u64 v) {
    float2 r; asm("mov.b64 {%0, %1}, %2;" : "=f"(r.x), "=f"(r.y) : "l"(v)); return r;
}

// ---------------- mma.sync / ldmatrix helpers (arch-agnostic, sm_80+) ------
__device__ __forceinline__ uint32_t smem_u32(const void* p) {
    uint32_t a;
    asm("{ .reg .u64 tmp; cvta.to.shared.u64 tmp, %1; cvt.u32.u64 %0, tmp; }"
        : "=r"(a) : "l"(p));
    return a;
}
#define LDSM_X4(r0, r1, r2, r3, addr) \
    asm volatile("ldmatrix.sync.aligned.m8n8.x4.shared.b16 {%0,%1,%2,%3}, [%4];" \
        : "=r"(r0), "=r"(r1), "=r"(r2), "=r"(r3) : "r"(addr))

__device__ __forceinline__ void mma_bf16(float c[4], const uint32_t a[4], const uint32_t b[2]) {
    asm volatile("mma.sync.aligned.m16n8k16.row.col.f32.bf16.bf16.f32 "
        "{%0,%1,%2,%3}, {%4,%5,%6,%7}, {%8,%9}, {%0,%1,%2,%3};"
        : "+f"(c[0]), "+f"(c[1]), "+f"(c[2]), "+f"(c[3])
        : "r"(a[0]), "r"(a[1]), "r"(a[2]), "r"(a[3]), "r"(b[0]), "r"(b[1]));
}

// split fp32 pair -> hi (truncated bf16) pair + lo (bf16 of residual) pair.
// packed b32: first operand in low 16 bits (memory order a, b).
__device__ __forceinline__ void cvt_pair(float a, float b, uint32_t& hi2, uint32_t& lo2) {
    uint32_t ua = __float_as_uint(a), ub = __float_as_uint(b);
    hi2 = __byte_perm(ua, ub, 0x7632);
    float ra = a - __uint_as_float(ua & 0xffff0000u);
    float rb = b - __uint_as_float(ub & 0xffff0000u);
    asm("cvt.rn.bf16x2.f32 %0, %1, %2;" : "=r"(lo2) : "f"(rb), "f"(ra));
}

// ---------------- scratch ----------------
__device__ float g_Q0[NB * INNER * YD];
__device__ float g_Q1[NB * INNER * YD];
__device__ float g_KV0[NB * 2 * INNER * WW];
__device__ float g_KV1[NB * 2 * INNER * WW];
__device__ float g_O0[(size_t)NB * YD * INNER];
__device__ float g_O1[(size_t)NB * YD * INNER];

// SMEM tile: 128 rows x 32 bf16, padded to 40 bf16 (80 B = 5x16B, conflict-free ldmatrix)
#define SROW 40

// Stage 128 rows x 32 k of fp32 (row-major, leading dim ld) into hi/lo bf16 tiles.
__device__ __forceinline__ void load_rows32(
    const float* __restrict__ src, size_t ld,
    uint16_t* hiB, uint16_t* loB, int t)
{
    int row = t >> 1, ks = (t & 1) * 16;
    const float4* p = (const float4*)(src + (size_t)row * ld + ks);
    float4 f0 = p[0], f1 = p[1], f2 = p[2], f3 = p[3];
    uint32_t h[8], l[8];
    cvt_pair(f0.x, f0.y, h[0], l[0]); cvt_pair(f0.z, f0.w, h[1], l[1]);
    cvt_pair(f1.x, f1.y, h[2], l[2]); cvt_pair(f1.z, f1.w, h[3], l[3]);
    cvt_pair(f2.x, f2.y, h[4], l[4]); cvt_pair(f2.z, f2.w, h[5], l[5]);
    cvt_pair(f3.x, f3.y, h[6], l[6]); cvt_pair(f3.z, f3.w, h[7], l[7]);
    char* dh = (char*)hiB + row * (SROW * 2) + ks * 2;
    char* dl = (char*)loB + row * (SROW * 2) + ks * 2;
    *(uint4*)dh       = make_uint4(h[0], h[1], h[2], h[3]);
    *((uint4*)dh + 1) = make_uint4(h[4], h[5], h[6], h[7]);
    *(uint4*)dl       = make_uint4(l[0], l[1], l[2], l[3]);
    *((uint4*)dl + 1) = make_uint4(l[4], l[5], l[6], l[7]);
}

// One BK=32 chunk of warp-level MMA work (3-pass hi/lo split).
__device__ __forceinline__ void mma_chunk(
    uint32_t aHi, uint32_t aLo, uint32_t bHi, uint32_t bLo,
    float acc[4][4][4], int lane, int wm, int wn)
{
    const int arow  = lane & 15;
    const int acol8 = (lane >> 4) * 8;
    const int brow  = ((lane >> 4) & 1) * 8 + (lane & 7);
    const int bcol8 = ((lane >> 3) & 1) * 8;
#pragma unroll
    for (int ks = 0; ks < 32; ks += 16) {
        uint32_t ah[4][4], al[4][4], bh[4][2], bl[4][2];
#pragma unroll
        for (int mt = 0; mt < 4; mt++) {
            uint32_t off = (uint32_t)(wm + mt * 16 + arow) * (SROW * 2) + (ks + acol8) * 2;
            LDSM_X4(ah[mt][0], ah[mt][1], ah[mt][2], ah[mt][3], aHi + off);
            LDSM_X4(al[mt][0], al[mt][1], al[mt][2], al[mt][3], aLo + off);
        }
#pragma unroll
        for (int np = 0; np < 2; np++) {
            uint32_t off = (uint32_t)(wn + np * 16 + brow) * (SROW * 2) + (ks + bcol8) * 2;
            LDSM_X4(bh[np*2][0], bh[np*2][1], bh[np*2+1][0], bh[np*2+1][1], bHi + off);
            LDSM_X4(bl[np*2][0], bl[np*2][1], bl[np*2+1][0], bl[np*2+1][1], bLo + off);
        }
#pragma unroll
        for (int mt = 0; mt < 4; mt++)
#pragma unroll
            for (int nt = 0; nt < 4; nt++) {
                mma_bf16(acc[mt][nt], ah[mt], bh[nt]);
                mma_bf16(acc[mt][nt], ah[mt], bl[nt]);
                mma_bf16(acc[mt][nt], al[mt], bh[nt]);
            }
    }
}

__device__ __forceinline__ void store_c(
    float* C, size_t ldc, int m0, int n0,
    float acc[4][4][4], int lane, int wm, int wn)
{
    int g = lane >> 2, tt = lane & 3;
#pragma unroll
    for (int mt = 0; mt < 4; mt++) {
        int r = m0 + wm + mt * 16 + g;
#pragma unroll
        for (int nt = 0; nt < 4; nt++) {
            int cc = n0 + wn + nt * 8 + 2 * tt;
            *(float2*)&C[(size_t)r * ldc + cc]       = make_float2(acc[mt][nt][0], acc[mt][nt][1]);
            *(float2*)&C[(size_t)(r + 8) * ldc + cc] = make_float2(acc[mt][nt][2], acc[mt][nt][3]);
        }
    }
}

#define GEMM_PROLOG \
    __shared__ __align__(16) uint16_t sAhi[128 * SROW], sAlo[128 * SROW]; \
    __shared__ __align__(16) uint16_t sBhi[128 * SROW], sBlo[128 * SROW]; \
    const int t = threadIdx.x, lane = t & 31, wid = t >> 5; \
    const int wm = (wid & 1) * 64, wn = (wid >> 1) * 32; \
    const uint32_t aHi = smem_u32(sAhi), aLo = smem_u32(sAlo); \
    const uint32_t bHi = smem_u32(sBhi), bLo = smem_u32(sBlo); \
    float acc[4][4][4]; \
    _Pragma("unroll") for (int i = 0; i < 4; i++) \
    _Pragma("unroll") for (int j = 0; j < 4; j++) \
    _Pragma("unroll") for (int q = 0; q < 4; q++) acc[i][j][q] = 0.f;

// =====================================================================
// Q projection. C[b,m,n] = sum_k A[m,k] X[b,k,n]. M=512,K=256,N=4096.
// grid(32, 4, 16), 256 thr.
// =====================================================================
__global__ __launch_bounds__(256) void qproj_tc(
    const float* __restrict__ A0, const float* __restrict__ X0, float* __restrict__ C0,
    const float* __restrict__ A1, const float* __restrict__ X1, float* __restrict__ C1)
{
    GEMM_PROLOG
    const int z = blockIdx.z, b = z & 7;
    const int m0 = blockIdx.y * 128, n0 = blockIdx.x * 128;
    const float* A = ((z < 8) ? A0 : A1) + (size_t)m0 * DIM;
    const float* X = ((z < 8) ? X0 : X1) + (size_t)b * DIM * YD;
    float*       C = ((z < 8) ? C0 : C1) + (size_t)b * INNER * YD;

    const int k2 = t >> 4, nl0 = t & 15;
    for (int c = 0; c < 8; c++) {
        const int k0 = c * 32;
        if (c) __syncthreads();
        load_rows32(A + k0, DIM, sAhi, sAlo, t);
        {   // B[n][k] from X[k][n] (transpose during staging)
            const float* xr0 = &X[(size_t)(k0 + 2 * k2) * YD + n0];
            const float* xr1 = xr0 + YD;
#pragma unroll
            for (int j = 0; j < 8; j++) {
                int nl = nl0 + 16 * j;
                uint32_t h, l;
                cvt_pair(xr0[nl], xr1[nl], h, l);
                *(uint32_t*)((char*)sBhi + nl * (SROW * 2) + k2 * 4) = h;
                *(uint32_t*)((char*)sBlo + nl * (SROW * 2) + k2 * 4) = l;
            }
        }
        __syncthreads();
        mma_chunk(aHi, aLo, bHi, bLo, acc, lane, wm, wn);
    }
    store_c(C, YD, m0, n0, acc, lane, wm, wn);
}

// =====================================================================
// KV projection. C[b,o,w] = sum_{n,pq} Wkv[o,n*16+pq] x[b,n,w*16+pq]
// M=1024,K=4096,N(w)=256. grid(2, 8, 16), 256 thr, 128 chunks.
// =====================================================================
__global__ __launch_bounds__(256) void kvproj_tc(
    const float* __restrict__ W0, const float* __restrict__ X0, float* __restrict__ C0,
    const float* __restrict__ W1, const float* __restrict__ X1, float* __restrict__ C1)
{
    GEMM_PROLOG
    const int z = blockIdx.z, b = z & 7;
    const int m0 = blockIdx.y * 128, w0 = blockIdx.x * 128;
    const int K = DIM * 16;
    const float* A  = ((z < 8) ? W0 : W1) + (size_t)m0 * K;
    const float* xp = ((z < 8) ? X0 : X1) + (size_t)b * DIM * YD;
    float*       C  = ((z < 8) ? C0 : C1) + (size_t)b * 2 * INNER * WW;

    const int p = t >> 7, wl = t & 127;
    for (int c = 0; c < 128; c++) {
        if (c) __syncthreads();
        load_rows32(A + c * 32, K, sAhi, sAlo, t);
        {   // B[w][kk]: kk = p*16+pq, source rows 2c, 2c+1 of x (contiguous per w)
            const float4* src = (const float4*)(xp + (size_t)(2 * c + p) * YD + (size_t)(w0 + wl) * 16);
            float4 f0 = src[0], f1 = src[1], f2 = src[2], f3 = src[3];
            uint32_t h[8], l[8];
            cvt_pair(f0.x, f0.y, h[0], l[0]); cvt_pair(f0.z, f0.w, h[1], l[1]);
            cvt_pair(f1.x, f1.y, h[2], l[2]); cvt_pair(f1.z, f1.w, h[3], l[3]);
            cvt_pair(f2.x, f2.y, h[4], l[4]); cvt_pair(f2.z, f2.w, h[5], l[5]);
            cvt_pair(f3.x, f3.y, h[6], l[6]); cvt_pair(f3.z, f3.w, h[7], l[7]);
            char* dh = (char*)sBhi + wl * (SROW * 2) + p * 32;
            char* dl = (char*)sBlo + wl * (SROW * 2) + p * 32;
            *(uint4*)dh       = make_uint4(h[0], h[1], h[2], h[3]);
            *((uint4*)dh + 1) = make_uint4(h[4], h[5], h[6], h[7]);
            *(uint4*)dl       = make_uint4(l[0], l[1], l[2], l[3]);
            *((uint4*)dl + 1) = make_uint4(l[4], l[5], l[6], l[7]);
        }
        __syncthreads();
        mma_chunk(aHi, aLo, bHi, bLo, acc, lane, wm, wn);
    }
    store_c(C, WW, m0, w0, acc, lane, wm, wn);
}

// =====================================================================
// Attention (unchanged f32x2 SIMT)
// =====================================================================
__global__ __launch_bounds__(256) void attn_kernel(
    const float* __restrict__ Q0, const float* __restrict__ KVa, float* __restrict__ O0,
    const float* __restrict__ Q1, const float* __restrict__ KVb, float* __restrict__ O1)
{
    const int z = blockIdx.z;
    const int b = z & 7;
    const float* Q  = (z < NB) ? Q0 : Q1;
    const float* KV = (z < NB) ? KVa : KVb;
    float*       O  = (z < NB) ? O0 : O1;
    const int h  = blockIdx.y;
    const int i0 = blockIdx.x * 64;

    extern __shared__ float sm[];
    float* ks = sm;
    float* vs = ks + 64 * 260;
    float* ps = vs + 64 * 260;
    float* qs = ps + 64 * 260;

    const int t = threadIdx.x, tx = t & 15, ty = t >> 4;

    const float* Kb = KV + ((size_t)b * 1024 + h * 64) * WW;
    const float* Vb = KV + ((size_t)b * 1024 + 512 + h * 64) * WW;

    for (int idx = t; idx < 64 * 64; idx += 256) {
        int d = idx >> 6, j4 = (idx & 63) * 4;
        *(float4*)&ks[d * 260 + j4] = *(const float4*)&Kb[d * WW + j4];
        *(float4*)&vs[d * 260 + j4] = *(const float4*)&Vb[d * WW + j4];
    }
    for (int idx = t; idx < 64 * 16; idx += 256) {
        int d = idx >> 4, i4 = (idx & 15) * 4;
        *(float4*)&qs[d * 68 + i4] =
            *(const float4*)&Q[((size_t)b * INNER + h * 64 + d) * YD + i0 + i4];
    }
    __syncthreads();

    u64 s2[4][8];
#pragma unroll
    for (int i = 0; i < 4; i++)
#pragma unroll
        for (int j = 0; j < 8; j++) s2[i][j] = 0ULL;

#pragma unroll 8
    for (int d = 0; d < 64; d++) {
        float4 q4 = *(const float4*)&qs[d * 68 + ty * 4];
        u64 qd[4] = { dup2(q4.x), dup2(q4.y), dup2(q4.z), dup2(q4.w) };
#pragma unroll
        for (int c = 0; c < 4; c++) {
            ulonglong2 kk = *(const ulonglong2*)&ks[d * 260 + c * 64 + tx * 4];
#pragma unroll
            for (int ii = 0; ii < 4; ii++) {
                s2[ii][c * 2 + 0] = ffma2(qd[ii], kk.x, s2[ii][c * 2 + 0]);
                s2[ii][c * 2 + 1] = ffma2(qd[ii], kk.y, s2[ii][c * 2 + 1]);
            }
        }
    }

    float p[4][16];
#pragma unroll
    for (int ii = 0; ii < 4; ii++) {
        float mx = -1e30f;
#pragma unroll
        for (int jp = 0; jp < 8; jp++) {
            float2 f = u2f(s2[ii][jp]);
            p[ii][jp * 2 + 0] = f.x * ASCALE;
            p[ii][jp * 2 + 1] = f.y * ASCALE;
            mx = fmaxf(mx, fmaxf(p[ii][jp * 2], p[ii][jp * 2 + 1]));
        }
#pragma unroll
        for (int off = 8; off; off >>= 1)
            mx = fmaxf(mx, __shfl_xor_sync(0xffffffffu, mx, off));
        float s = 0.f;
#pragma unroll
        for (int w = 0; w < 16; w++) { p[ii][w] = __expf(p[ii][w] - mx); s += p[ii][w]; }
#pragma unroll
        for (int off = 8; off; off >>= 1)
            s += __shfl_xor_sync(0xffffffffu, s, off);
        float inv = 1.f / s;
#pragma unroll
        for (int w = 0; w < 16; w++) p[ii][w] *= inv;
    }
#pragma unroll
    for (int ii = 0; ii < 4; ii++) {
        int row = ty * 4 + ii;
#pragma unroll
        for (int c = 0; c < 4; c++) {
            float4 v;
            v.x = p[ii][c * 4 + 0]; v.y = p[ii][c * 4 + 1];
            v.z = p[ii][c * 4 + 2]; v.w = p[ii][c * 4 + 3];
            *(float4*)&ps[row * 260 + c * 64 + tx * 4] = v;
        }
    }
    __syncthreads();

    u64 o2[4][4];
#pragma unroll
    for (int i = 0; i < 4; i++)
#pragma unroll
        for (int j = 0; j < 4; j++) o2[i][j] = 0ULL;

#pragma unroll 8
    for (int j = 0; j < 256; j += 4) {
        ulonglong2 av[4], bv[4];
#pragma unroll
        for (int ii = 0; ii < 4; ii++)
            av[ii] = *(const ulonglong2*)&ps[(ty * 4 + ii) * 260 + j];
#pragma unroll
        for (int r = 0; r < 4; r++)
            bv[r] = *(const ulonglong2*)&vs[(tx + 16 * r) * 260 + j];
#pragma unroll
        for (int ii = 0; ii < 4; ii++)
#pragma unroll
            for (int r = 0; r < 4; r++) {
                o2[ii][r] = ffma2(av[ii].x, bv[r].x, o2[ii][r]);
                o2[ii][r] = ffma2(av[ii].y, bv[r].y, o2[ii][r]);
            }
    }
#pragma unroll
    for (int ii = 0; ii < 4; ii++) {
        size_t base = (((size_t)b * YD + i0 + ty * 4 + ii) * HH + h) * 64;
#pragma unroll
        for (int r = 0; r < 4; r++) {
            float2 f = u2f(o2[ii][r]);
            O[base + tx + 16 * r] = f.x + f.y;
        }
    }
}

// =====================================================================
// Out projection (NT, both phases into one accumulator) + residual fuse.
// M=256,N=4096,K=512x2. grid(32, 2, 8), 256 thr, 32 chunks.
// =====================================================================
__global__ __launch_bounds__(256) void outproj_tc(
    const float* __restrict__ W0, const float* __restrict__ O0,
    const float* __restrict__ W1, const float* __restrict__ O1,
    const float* __restrict__ b0, const float* __restrict__ b1,
    const float* __restrict__ x0, const float* __restrict__ x1,
    float* __restrict__ out)
{
    GEMM_PROLOG
    const int b = blockIdx.z;
    const int m0 = blockIdx.y * 128, n0 = blockIdx.x * 128;

    for (int c = 0; c < 32; c++) {
        const int phs = c >> 4;
        const int k0  = (c & 15) * 32;
        const float* A  = ((phs == 0) ? W0 : W1) + (size_t)m0 * INNER;
        const float* Op = ((phs == 0) ? O0 : O1) + ((size_t)b * YD + n0) * INNER;
        if (c) __syncthreads();
        load_rows32(A + k0, INNER, sAhi, sAlo, t);
        load_rows32(Op + k0, INNER, sBhi, sBlo, t);
        __syncthreads();
        mma_chunk(aHi, aLo, bHi, bLo, acc, lane, wm, wn);
    }

    // epilogue with residual fuse
    const int g = lane >> 2, tt = lane & 3;
#pragma unroll
    for (int mt = 0; mt < 4; mt++) {
        int r = m0 + wm + mt * 16 + g;
        float biasA = 0.5f * (b0[r] + b1[r]);
        float biasB = 0.5f * (b0[r + 8] + b1[r + 8]);
#pragma unroll
        for (int nt = 0; nt < 4; nt++) {
            int cc = n0 + wn + nt * 8 + 2 * tt;
            size_t iA = ((size_t)b * DIM + r) * YD + cc;
            size_t iB = ((size_t)b * DIM + r + 8) * YD + cc;
            float2 xa = *(const float2*)&x0[iA], xb = *(const float2*)&x1[iA];
            float2 o;
            o.x = 0.5f * (acc[mt][nt][0] + xa.x + xb.x) + biasA;
            o.y = 0.5f * (acc[mt][nt][1] + xa.y + xb.y) + biasA;
            *(float2*)&out[iA] = o;
            xa = *(const float2*)&x0[iB]; xb = *(const float2*)&x1[iB];
            o.x = 0.5f * (acc[mt][nt][2] + xa.x + xb.x) + biasB;
            o.y = 0.5f * (acc[mt][nt][3] + xa.y + xb.y) + biasB;
            *(float2*)&out[iB] = o;
        }
    }
}

// =====================================================================
extern "C" void kernel_launch(void* const* d_in, const int* in_sizes, int n_in,
                              void* d_out, int out_size)
{
    const float* x0    = (const float*)d_in[0];
    const float* x1    = (const float*)d_in[1];
    const float* Wq0   = (const float*)d_in[2];
    const float* Wkv0  = (const float*)d_in[3];
    const float* Wq1   = (const float*)d_in[4];
    const float* Wkv1  = (const float*)d_in[5];
    const float* Wout0 = (const float*)d_in[6];
    const float* bout0 = (const float*)d_in[7];
    const float* Wout1 = (const float*)d_in[8];
    const float* bout1 = (const float*)d_in[9];
    float* out = (float*)d_out;

    float *Q0, *Q1, *KV0, *KV1, *O0, *O1;
    cudaGetSymbolAddress((void**)&Q0,  g_Q0);
    cudaGetSymbolAddress((void**)&Q1,  g_Q1);
    cudaGetSymbolAddress((void**)&KV0, g_KV0);
    cudaGetSymbolAddress((void**)&KV1, g_KV1);
    cudaGetSymbolAddress((void**)&O0,  g_O0);
    cudaGetSymbolAddress((void**)&O1,  g_O1);

    const int attn_smem = (3 * 64 * 260 + 64 * 68) * (int)sizeof(float);
    cudaFuncSetAttribute(attn_kernel, cudaFuncAttributeMaxDynamicSharedMemorySize, attn_smem);

    qproj_tc<<<dim3(YD / 128, INNER / 128, 2 * NB), 256>>>(Wq0, x0, Q0, Wq1, x1, Q1);
    kvproj_tc<<<dim3(WW / 128, (2 * INNER) / 128, 2 * NB), 256>>>(Wkv0, x0, KV0, Wkv1, x1, KV1);
    attn_kernel<<<dim3(YD / 64, HH, 2 * NB), 256, attn_smem>>>(Q0, KV1, O0, Q1, KV0, O1);
    outproj_tc<<<dim3(YD / 128, DIM / 128, NB), 256>>>(
        Wout0, O0, Wout1, O1, bout0, bout1, x0, x1, out);
}

// round 6
// speedup vs baseline: 2.8270x; 1.8506x over previous
#include <cuda_runtime.h>
#include <math.h>
#include <cstdint>

#define NB    8
#define DIM   256
#define YD    4096
#define HH    8
#define INNER 512
#define WW    256
#define ASCALE 0.125f

// ---------------- mma.sync / ldmatrix helpers (arch-agnostic, sm_80+) ------
__device__ __forceinline__ uint32_t smem_u32(const void* p) {
    uint32_t a;
    asm("{ .reg .u64 tmp; cvta.to.shared.u64 tmp, %1; cvt.u32.u64 %0, tmp; }"
        : "=r"(a) : "l"(p));
    return a;
}
#define LDSM_X4(r0, r1, r2, r3, addr) \
    asm volatile("ldmatrix.sync.aligned.m8n8.x4.shared.b16 {%0,%1,%2,%3}, [%4];" \
        : "=r"(r0), "=r"(r1), "=r"(r2), "=r"(r3) : "r"(addr))

__device__ __forceinline__ void mma_bf16(float c[4], const uint32_t a[4], const uint32_t b[2]) {
    asm volatile("mma.sync.aligned.m16n8k16.row.col.f32.bf16.bf16.f32 "
        "{%0,%1,%2,%3}, {%4,%5,%6,%7}, {%8,%9}, {%0,%1,%2,%3};"
        : "+f"(c[0]), "+f"(c[1]), "+f"(c[2]), "+f"(c[3])
        : "r"(a[0]), "r"(a[1]), "r"(a[2]), "r"(a[3]), "r"(b[0]), "r"(b[1]));
}

// split fp32 pair -> hi (truncated bf16) pair + lo (bf16 of residual) pair.
__device__ __forceinline__ void cvt_pair(float a, float b, uint32_t& hi2, uint32_t& lo2) {
    uint32_t ua = __float_as_uint(a), ub = __float_as_uint(b);
    hi2 = __byte_perm(ua, ub, 0x7632);
    float ra = a - __uint_as_float(ua & 0xffff0000u);
    float rb = b - __uint_as_float(ub & 0xffff0000u);
    asm("cvt.rn.bf16x2.f32 %0, %1, %2;" : "=r"(lo2) : "f"(rb), "f"(ra));
}

// ---------------- scratch ----------------
__device__ float g_Q0[NB * INNER * YD];
__device__ float g_Q1[NB * INNER * YD];
__device__ float g_KV0[NB * 2 * INNER * WW];
__device__ float g_KV1[NB * 2 * INNER * WW];
__device__ float g_O0[(size_t)NB * YD * INNER];
__device__ float g_O1[(size_t)NB * YD * INNER];

// SMEM tile for GEMMs: 128 rows x 32 bf16, padded to 40 (80 B = 5x16B)
#define SROW 40

__device__ __forceinline__ void load_rows32(
    const float* __restrict__ src, size_t ld,
    uint16_t* hiB, uint16_t* loB, int t)
{
    int row = t >> 1, ks = (t & 1) * 16;
    const float4* p = (const float4*)(src + (size_t)row * ld + ks);
    float4 f0 = p[0], f1 = p[1], f2 = p[2], f3 = p[3];
    uint32_t h[8], l[8];
    cvt_pair(f0.x, f0.y, h[0], l[0]); cvt_pair(f0.z, f0.w, h[1], l[1]);
    cvt_pair(f1.x, f1.y, h[2], l[2]); cvt_pair(f1.z, f1.w, h[3], l[3]);
    cvt_pair(f2.x, f2.y, h[4], l[4]); cvt_pair(f2.z, f2.w, h[5], l[5]);
    cvt_pair(f3.x, f3.y, h[6], l[6]); cvt_pair(f3.z, f3.w, h[7], l[7]);
    char* dh = (char*)hiB + row * (SROW * 2) + ks * 2;
    char* dl = (char*)loB + row * (SROW * 2) + ks * 2;
    *(uint4*)dh       = make_uint4(h[0], h[1], h[2], h[3]);
    *((uint4*)dh + 1) = make_uint4(h[4], h[5], h[6], h[7]);
    *(uint4*)dl       = make_uint4(l[0], l[1], l[2], l[3]);
    *((uint4*)dl + 1) = make_uint4(l[4], l[5], l[6], l[7]);
}

__device__ __forceinline__ void mma_chunk(
    uint32_t aHi, uint32_t aLo, uint32_t bHi, uint32_t bLo,
    float acc[4][4][4], int lane, int wm, int wn)
{
    const int arow  = lane & 15;
    const int acol8 = (lane >> 4) * 8;
    const int brow  = ((lane >> 4) & 1) * 8 + (lane & 7);
    const int bcol8 = ((lane >> 3) & 1) * 8;
#pragma unroll
    for (int ks = 0; ks < 32; ks += 16) {
        uint32_t ah[4][4], al[4][4], bh[4][2], bl[4][2];
#pragma unroll
        for (int mt = 0; mt < 4; mt++) {
            uint32_t off = (uint32_t)(wm + mt * 16 + arow) * (SROW * 2) + (ks + acol8) * 2;
            LDSM_X4(ah[mt][0], ah[mt][1], ah[mt][2], ah[mt][3], aHi + off);
            LDSM_X4(al[mt][0], al[mt][1], al[mt][2], al[mt][3], aLo + off);
        }
#pragma unroll
        for (int np = 0; np < 2; np++) {
            uint32_t off = (uint32_t)(wn + np * 16 + brow) * (SROW * 2) + (ks + bcol8) * 2;
            LDSM_X4(bh[np*2][0], bh[np*2][1], bh[np*2+1][0], bh[np*2+1][1], bHi + off);
            LDSM_X4(bl[np*2][0], bl[np*2][1], bl[np*2+1][0], bl[np*2+1][1], bLo + off);
        }
#pragma unroll
        for (int mt = 0; mt < 4; mt++)
#pragma unroll
            for (int nt = 0; nt < 4; nt++) {
                mma_bf16(acc[mt][nt], ah[mt], bh[nt]);
                mma_bf16(acc[mt][nt], ah[mt], bl[nt]);
                mma_bf16(acc[mt][nt], al[mt], bh[nt]);
            }
    }
}

__device__ __forceinline__ void store_c(
    float* C, size_t ldc, int m0, int n0,
    float acc[4][4][4], int lane, int wm, int wn)
{
    int g = lane >> 2, tt = lane & 3;
#pragma unroll
    for (int mt = 0; mt < 4; mt++) {
        int r = m0 + wm + mt * 16 + g;
#pragma unroll
        for (int nt = 0; nt < 4; nt++) {
            int cc = n0 + wn + nt * 8 + 2 * tt;
            *(float2*)&C[(size_t)r * ldc + cc]       = make_float2(acc[mt][nt][0], acc[mt][nt][1]);
            *(float2*)&C[(size_t)(r + 8) * ldc + cc] = make_float2(acc[mt][nt][2], acc[mt][nt][3]);
        }
    }
}

#define GEMM_PROLOG \
    __shared__ __align__(16) uint16_t sAhi[128 * SROW], sAlo[128 * SROW]; \
    __shared__ __align__(16) uint16_t sBhi[128 * SROW], sBlo[128 * SROW]; \
    const int t = threadIdx.x, lane = t & 31, wid = t >> 5; \
    const int wm = (wid & 1) * 64, wn = (wid >> 1) * 32; \
    const uint32_t aHi = smem_u32(sAhi), aLo = smem_u32(sAlo); \
    const uint32_t bHi = smem_u32(sBhi), bLo = smem_u32(sBlo); \
    float acc[4][4][4]; \
    _Pragma("unroll") for (int i = 0; i < 4; i++) \
    _Pragma("unroll") for (int j = 0; j < 4; j++) \
    _Pragma("unroll") for (int q = 0; q < 4; q++) acc[i][j][q] = 0.f;

// =====================================================================
// Q projection. M=512,K=256,N=4096. grid(32,4,16), 256 thr.
// =====================================================================
__global__ __launch_bounds__(256) void qproj_tc(
    const float* __restrict__ A0, const float* __restrict__ X0, float* __restrict__ C0,
    const float* __restrict__ A1, const float* __restrict__ X1, float* __restrict__ C1)
{
    GEMM_PROLOG
    const int z = blockIdx.z, b = z & 7;
    const int m0 = blockIdx.y * 128, n0 = blockIdx.x * 128;
    const float* A = ((z < 8) ? A0 : A1) + (size_t)m0 * DIM;
    const float* X = ((z < 8) ? X0 : X1) + (size_t)b * DIM * YD;
    float*       C = ((z < 8) ? C0 : C1) + (size_t)b * INNER * YD;

    const int k2 = t >> 4, nl0 = t & 15;
    for (int c = 0; c < 8; c++) {
        const int k0 = c * 32;
        if (c) __syncthreads();
        load_rows32(A + k0, DIM, sAhi, sAlo, t);
        {
            const float* xr0 = &X[(size_t)(k0 + 2 * k2) * YD + n0];
            const float* xr1 = xr0 + YD;
#pragma unroll
            for (int j = 0; j < 8; j++) {
                int nl = nl0 + 16 * j;
                uint32_t h, l;
                cvt_pair(xr0[nl], xr1[nl], h, l);
                *(uint32_t*)((char*)sBhi + nl * (SROW * 2) + k2 * 4) = h;
                *(uint32_t*)((char*)sBlo + nl * (SROW * 2) + k2 * 4) = l;
            }
        }
        __syncthreads();
        mma_chunk(aHi, aLo, bHi, bLo, acc, lane, wm, wn);
    }
    store_c(C, YD, m0, n0, acc, lane, wm, wn);
}

// =====================================================================
// KV projection. M=1024,K=4096,N(w)=256. grid(2,8,16), 256 thr.
// =====================================================================
__global__ __launch_bounds__(256) void kvproj_tc(
    const float* __restrict__ W0, const float* __restrict__ X0, float* __restrict__ C0,
    const float* __restrict__ W1, const float* __restrict__ X1, float* __restrict__ C1)
{
    GEMM_PROLOG
    const int z = blockIdx.z, b = z & 7;
    const int m0 = blockIdx.y * 128, w0 = blockIdx.x * 128;
    const int K = DIM * 16;
    const float* A  = ((z < 8) ? W0 : W1) + (size_t)m0 * K;
    const float* xp = ((z < 8) ? X0 : X1) + (size_t)b * DIM * YD;
    float*       C  = ((z < 8) ? C0 : C1) + (size_t)b * 2 * INNER * WW;

    const int p = t >> 7, wl = t & 127;
    for (int c = 0; c < 128; c++) {
        if (c) __syncthreads();
        load_rows32(A + c * 32, K, sAhi, sAlo, t);
        {
            const float4* src = (const float4*)(xp + (size_t)(2 * c + p) * YD + (size_t)(w0 + wl) * 16);
            float4 f0 = src[0], f1 = src[1], f2 = src[2], f3 = src[3];
            uint32_t h[8], l[8];
            cvt_pair(f0.x, f0.y, h[0], l[0]); cvt_pair(f0.z, f0.w, h[1], l[1]);
            cvt_pair(f1.x, f1.y, h[2], l[2]); cvt_pair(f1.z, f1.w, h[3], l[3]);
            cvt_pair(f2.x, f2.y, h[4], l[4]); cvt_pair(f2.z, f2.w, h[5], l[5]);
            cvt_pair(f3.x, f3.y, h[6], l[6]); cvt_pair(f3.z, f3.w, h[7], l[7]);
            char* dh = (char*)sBhi + wl * (SROW * 2) + p * 32;
            char* dl = (char*)sBlo + wl * (SROW * 2) + p * 32;
            *(uint4*)dh       = make_uint4(h[0], h[1], h[2], h[3]);
            *((uint4*)dh + 1) = make_uint4(h[4], h[5], h[6], h[7]);
            *(uint4*)dl       = make_uint4(l[0], l[1], l[2], l[3]);
            *((uint4*)dl + 1) = make_uint4(l[4], l[5], l[6], l[7]);
        }
        __syncthreads();
        mma_chunk(aHi, aLo, bHi, bLo, acc, lane, wm, wn);
    }
    store_c(C, WW, m0, w0, acc, lane, wm, wn);
}

// =====================================================================
// Attention via mma.sync. CTA = 128 q rows x (b,h,stream); 8 warps x 16 rows.
// K [j][d] hi/lo, V [d][j] hi/lo, Q [i][d] hi/lo in SMEM. Full 256-col
// scores in registers; warp-local softmax; P->A-fragment direct convert.
// =====================================================================
#define QROW_B 144      // 72 bf16 per row
#define VROW_B 528      // 264 bf16 per row
#define ATTN_SMEM 178176

__global__ __launch_bounds__(256, 1) void attn_tc(
    const float* __restrict__ Q0, const float* __restrict__ KVa, float* __restrict__ O0,
    const float* __restrict__ Q1, const float* __restrict__ KVb, float* __restrict__ O1)
{
    extern __shared__ char sm[];
    const int z = blockIdx.z, b = z & 7;
    const float* Q  = (z < NB) ? Q0 : Q1;
    const float* KV = (z < NB) ? KVa : KVb;
    float*       O  = (z < NB) ? O0 : O1;
    const int h  = blockIdx.y;
    const int i0 = blockIdx.x * 128;

    char* sQh = sm;            char* sQl = sm + 18432;
    char* sKh = sm + 36864;    char* sKl = sm + 73728;
    char* sVh = sm + 110592;   char* sVl = sm + 144384;

    const int t = threadIdx.x, lane = t & 31, wid = t >> 5;

    const float* Qb = Q + ((size_t)b * INNER + h * 64) * YD + i0;
    const float* Kb = KV + ((size_t)b * 1024 + h * 64) * WW;
    const float* Vb = KV + ((size_t)b * 1024 + 512 + h * 64) * WW;

    // ---- stage Q [i][d] (transpose + hi/lo split) ----
#pragma unroll
    for (int u = 0; u < 16; u++) {
        int idx = u * 256 + t;
        int d2 = idx >> 7, i = idx & 127;
        float a = Qb[(size_t)(2 * d2) * YD + i];
        float c = Qb[(size_t)(2 * d2 + 1) * YD + i];
        uint32_t hh, ll; cvt_pair(a, c, hh, ll);
        *(uint32_t*)(sQh + i * QROW_B + d2 * 4) = hh;
        *(uint32_t*)(sQl + i * QROW_B + d2 * 4) = ll;
    }
    // ---- stage K [j][d] ----
#pragma unroll
    for (int u = 0; u < 32; u++) {
        int idx = u * 256 + t;
        int d2 = idx >> 8, j = idx & 255;
        float a = Kb[(size_t)(2 * d2) * WW + j];
        float c = Kb[(size_t)(2 * d2 + 1) * WW + j];
        uint32_t hh, ll; cvt_pair(a, c, hh, ll);
        *(uint32_t*)(sKh + j * QROW_B + d2 * 4) = hh;
        *(uint32_t*)(sKl + j * QROW_B + d2 * 4) = ll;
    }
    // ---- stage V [d][j] (no transpose) ----
#pragma unroll
    for (int u = 0; u < 16; u++) {
        int idx = u * 256 + t;
        int d = idx >> 6, j4 = (idx & 63) * 4;
        float4 f = *(const float4*)&Vb[(size_t)d * WW + j4];
        uint32_t h0, l0, h1, l1;
        cvt_pair(f.x, f.y, h0, l0); cvt_pair(f.z, f.w, h1, l1);
        *(uint2*)(sVh + d * VROW_B + j4 * 2) = make_uint2(h0, h1);
        *(uint2*)(sVl + d * VROW_B + j4 * 2) = make_uint2(l0, l1);
    }
    __syncthreads();

    const uint32_t uQh = smem_u32(sQh), uQl = smem_u32(sQl);
    const uint32_t uKh = smem_u32(sKh), uKl = smem_u32(sKl);
    const uint32_t uVh = smem_u32(sVh), uVl = smem_u32(sVl);

    const int arow  = lane & 15, acol8 = (lane >> 4) * 8;
    const int brow  = ((lane >> 4) & 1) * 8 + (lane & 7);
    const int bcol8 = ((lane >> 3) & 1) * 8;

    // ---- QK^T: 16 x 256 scores per warp ----
    float s[32][4];
#pragma unroll
    for (int nt = 0; nt < 32; nt++)
#pragma unroll
        for (int q = 0; q < 4; q++) s[nt][q] = 0.f;

#pragma unroll
    for (int kc = 0; kc < 4; kc++) {
        uint32_t ah[4], al[4];
        uint32_t aoff = (uint32_t)(wid * 16 + arow) * QROW_B + (kc * 16 + acol8) * 2;
        LDSM_X4(ah[0], ah[1], ah[2], ah[3], uQh + aoff);
        LDSM_X4(al[0], al[1], al[2], al[3], uQl + aoff);
#pragma unroll
        for (int np = 0; np < 16; np++) {
            uint32_t boff = (uint32_t)(np * 16 + brow) * QROW_B + (kc * 16 + bcol8) * 2;
            uint32_t bh[4], bl[4];
            LDSM_X4(bh[0], bh[1], bh[2], bh[3], uKh + boff);
            LDSM_X4(bl[0], bl[1], bl[2], bl[3], uKl + boff);
            mma_bf16(s[2*np],   ah, &bh[0]);
            mma_bf16(s[2*np],   ah, &bl[0]);
            mma_bf16(s[2*np],   al, &bh[0]);
            mma_bf16(s[2*np+1], ah, &bh[2]);
            mma_bf16(s[2*np+1], ah, &bl[2]);
            mma_bf16(s[2*np+1], al, &bh[2]);
        }
    }

    // ---- softmax (warp-local; rows g and g+8 of each warp's 16) ----
    float mx1 = -1e30f, mx2 = -1e30f;
#pragma unroll
    for (int nt = 0; nt < 32; nt++) {
        s[nt][0] *= ASCALE; s[nt][1] *= ASCALE;
        s[nt][2] *= ASCALE; s[nt][3] *= ASCALE;
        mx1 = fmaxf(mx1, fmaxf(s[nt][0], s[nt][1]));
        mx2 = fmaxf(mx2, fmaxf(s[nt][2], s[nt][3]));
    }
    mx1 = fmaxf(mx1, __shfl_xor_sync(0xffffffffu, mx1, 1));
    mx1 = fmaxf(mx1, __shfl_xor_sync(0xffffffffu, mx1, 2));
    mx2 = fmaxf(mx2, __shfl_xor_sync(0xffffffffu, mx2, 1));
    mx2 = fmaxf(mx2, __shfl_xor_sync(0xffffffffu, mx2, 2));
    float sum1 = 0.f, sum2 = 0.f;
#pragma unroll
    for (int nt = 0; nt < 32; nt++) {
        s[nt][0] = __expf(s[nt][0] - mx1); sum1 += s[nt][0];
        s[nt][1] = __expf(s[nt][1] - mx1); sum1 += s[nt][1];
        s[nt][2] = __expf(s[nt][2] - mx2); sum2 += s[nt][2];
        s[nt][3] = __expf(s[nt][3] - mx2); sum2 += s[nt][3];
    }
    sum1 += __shfl_xor_sync(0xffffffffu, sum1, 1);
    sum1 += __shfl_xor_sync(0xffffffffu, sum1, 2);
    sum2 += __shfl_xor_sync(0xffffffffu, sum2, 1);
    sum2 += __shfl_xor_sync(0xffffffffu, sum2, 2);
    const float i1 = 1.f / sum1, i2 = 1.f / sum2;

    // ---- P @ V: convert score fragments directly into A fragments ----
    float o[8][4];
#pragma unroll
    for (int dt = 0; dt < 8; dt++)
#pragma unroll
        for (int q = 0; q < 4; q++) o[dt][q] = 0.f;

#pragma unroll
    for (int kc = 0; kc < 16; kc++) {
        uint32_t ph[4], pl[4];
        cvt_pair(s[2*kc][0]   * i1, s[2*kc][1]   * i1, ph[0], pl[0]);
        cvt_pair(s[2*kc][2]   * i2, s[2*kc][3]   * i2, ph[1], pl[1]);
        cvt_pair(s[2*kc+1][0] * i1, s[2*kc+1][1] * i1, ph[2], pl[2]);
        cvt_pair(s[2*kc+1][2] * i2, s[2*kc+1][3] * i2, ph[3], pl[3]);
#pragma unroll
        for (int dp = 0; dp < 4; dp++) {
            uint32_t voff = (uint32_t)(dp * 16 + brow) * VROW_B + (kc * 16 + bcol8) * 2;
            uint32_t vh[4], vl[4];
            LDSM_X4(vh[0], vh[1], vh[2], vh[3], uVh + voff);
            LDSM_X4(vl[0], vl[1], vl[2], vl[3], uVl + voff);
            mma_bf16(o[2*dp],   ph, &vh[0]);
            mma_bf16(o[2*dp],   pl, &vh[0]);
            mma_bf16(o[2*dp],   ph, &vl[0]);
            mma_bf16(o[2*dp+1], ph, &vh[2]);
            mma_bf16(o[2*dp+1], pl, &vh[2]);
            mma_bf16(o[2*dp+1], ph, &vl[2]);
        }
    }

    // ---- write O[b][y][h*64+d] ----
    const int g = lane >> 2, tt = lane & 3;
    const int y = i0 + wid * 16 + g;
    size_t rb = ((size_t)b * YD + y) * INNER + h * 64;
#pragma unroll
    for (int dt = 0; dt < 8; dt++) {
        *(float2*)&O[rb + dt * 8 + 2 * tt] = make_float2(o[dt][0], o[dt][1]);
        *(float2*)&O[rb + (size_t)8 * INNER + dt * 8 + 2 * tt] = make_float2(o[dt][2], o[dt][3]);
    }
}

// =====================================================================
// Out projection (NT, both phases) + residual fuse. grid(32,2,8), 256 thr.
// =====================================================================
__global__ __launch_bounds__(256) void outproj_tc(
    const float* __restrict__ W0, const float* __restrict__ O0,
    const float* __restrict__ W1, const float* __restrict__ O1,
    const float* __restrict__ b0, const float* __restrict__ b1,
    const float* __restrict__ x0, const float* __restrict__ x1,
    float* __restrict__ out)
{
    GEMM_PROLOG
    const int b = blockIdx.z;
    const int m0 = blockIdx.y * 128, n0 = blockIdx.x * 128;

    for (int c = 0; c < 32; c++) {
        const int phs = c >> 4;
        const int k0  = (c & 15) * 32;
        const float* A  = ((phs == 0) ? W0 : W1) + (size_t)m0 * INNER;
        const float* Op = ((phs == 0) ? O0 : O1) + ((size_t)b * YD + n0) * INNER;
        if (c) __syncthreads();
        load_rows32(A + k0, INNER, sAhi, sAlo, t);
        load_rows32(Op + k0, INNER, sBhi, sBlo, t);
        __syncthreads();
        mma_chunk(aHi, aLo, bHi, bLo, acc, lane, wm, wn);
    }

    const int g = lane >> 2, tt = lane & 3;
#pragma unroll
    for (int mt = 0; mt < 4; mt++) {
        int r = m0 + wm + mt * 16 + g;
        float biasA = 0.5f * (b0[r] + b1[r]);
        float biasB = 0.5f * (b0[r + 8] + b1[r + 8]);
#pragma unroll
        for (int nt = 0; nt < 4; nt++) {
            int cc = n0 + wn + nt * 8 + 2 * tt;
            size_t iA = ((size_t)b * DIM + r) * YD + cc;
            size_t iB = ((size_t)b * DIM + r + 8) * YD + cc;
            float2 xa = *(const float2*)&x0[iA], xb = *(const float2*)&x1[iA];
            float2 oo;
            oo.x = 0.5f * (acc[mt][nt][0] + xa.x + xb.x) + biasA;
            oo.y = 0.5f * (acc[mt][nt][1] + xa.y + xb.y) + biasA;
            *(float2*)&out[iA] = oo;
            xa = *(const float2*)&x0[iB]; xb = *(const float2*)&x1[iB];
            oo.x = 0.5f * (acc[mt][nt][2] + xa.x + xb.x) + biasB;
            oo.y = 0.5f * (acc[mt][nt][3] + xa.y + xb.y) + biasB;
            *(float2*)&out[iB] = oo;
        }
    }
}

// =====================================================================
extern "C" void kernel_launch(void* const* d_in, const int* in_sizes, int n_in,
                              void* d_out, int out_size)
{
    const float* x0    = (const float*)d_in[0];
    const float* x1    = (const float*)d_in[1];
    const float* Wq0   = (const float*)d_in[2];
    const float* Wkv0  = (const float*)d_in[3];
    const float* Wq1   = (const float*)d_in[4];
    const float* Wkv1  = (const float*)d_in[5];
    const float* Wout0 = (const float*)d_in[6];
    const float* bout0 = (const float*)d_in[7];
    const float* Wout1 = (const float*)d_in[8];
    const float* bout1 = (const float*)d_in[9];
    float* out = (float*)d_out;

    float *Q0, *Q1, *KV0, *KV1, *O0, *O1;
    cudaGetSymbolAddress((void**)&Q0,  g_Q0);
    cudaGetSymbolAddress((void**)&Q1,  g_Q1);
    cudaGetSymbolAddress((void**)&KV0, g_KV0);
    cudaGetSymbolAddress((void**)&KV1, g_KV1);
    cudaGetSymbolAddress((void**)&O0,  g_O0);
    cudaGetSymbolAddress((void**)&O1,  g_O1);

    cudaFuncSetAttribute(attn_tc, cudaFuncAttributeMaxDynamicSharedMemorySize, ATTN_SMEM);

    qproj_tc<<<dim3(YD / 128, INNER / 128, 2 * NB), 256>>>(Wq0, x0, Q0, Wq1, x1, Q1);
    kvproj_tc<<<dim3(WW / 128, (2 * INNER) / 128, 2 * NB), 256>>>(Wkv0, x0, KV0, Wkv1, x1, KV1);
    attn_tc<<<dim3(YD / 128, HH, 2 * NB), 256, ATTN_SMEM>>>(Q0, KV1, O0, Q1, KV0, O1);
    outproj_tc<<<dim3(YD / 128, DIM / 128, NB), 256>>>(
        Wout0, O0, Wout1, O1, bout0, bout1, x0, x1, out);
}